// round 5
// baseline (speedup 1.0000x reference)
#include <cuda_runtime.h>
#include <stdint.h>

#define NSLOTS 4096
#define TPB_A 1024
#define PT 4            // NSLOTS / TPB_A
#define NBINS 4096
#define KPAD 672
#define NSLICE 4
#define TPB_B 512
#define EPSF 1e-3f

__device__ int g_idx[256 * KPAD];   // packed: slot | (present << 15)

// ======================= Kernel A: per-row selection =======================
__global__ __launch_bounds__(TPB_A) void select_kernel(
    const float* __restrict__ z_present,
    const float* __restrict__ neg_priority,
    int K)
{
    __shared__ unsigned int s_keys[NSLOTS];   // 16KB
    __shared__ int s_hist[NBINS];             // 16KB (reused as candidate list)
    __shared__ int s_wsum[32];
    __shared__ int s_scal[8];

    const int b    = blockIdx.x;
    const int tid  = threadIdx.x;
    const int lane = tid & 31;
    const int warp = tid >> 5;
    const int base = tid * PT;

    // ---- load presence + priority, build keys/digits ----
    int presf[PT], local[PT], digr[PT];
    int sum = 0;
    {
        float4 p = ((const float4*)(z_present    + (size_t)b * NSLOTS))[tid];
        float4 q = ((const float4*)(neg_priority + (size_t)b * NSLOTS))[tid];
        float pv[4] = {p.x, p.y, p.z, p.w};
        float qv[4] = {q.x, q.y, q.z, q.w};
        #pragma unroll
        for (int j = 0; j < PT; j++) {
            bool pres = pv[j] > EPSF;
            presf[j] = pres ? 1 : 0;
            local[j] = sum;
            sum += presf[j];
            unsigned int bits = __float_as_uint(qv[j]);
            unsigned int msk  = (unsigned int)(((int)bits) >> 31) | 0x80000000u;
            s_keys[base + j] = pres ? 0xFFFFFFFFu : (bits ^ msk);
            int d = __float2int_rd(qv[j] * 4096.0f);   // exact ×2^12, monotone
            digr[j] = min(NBINS - 1, max(0, d));
        }
    }
    ((int4*)s_hist)[tid] = make_int4(0, 0, 0, 0);       // zero histogram
    int ws = sum;
    #pragma unroll
    for (int o = 1; o < 32; o <<= 1) {
        int v = __shfl_up_sync(0xFFFFFFFFu, ws, o);
        if (lane >= o) ws += v;
    }
    if (lane == 31) s_wsum[warp] = ws;
    if (tid == 0) { s_scal[1] = -1; s_scal[4] = 0; }
    __syncthreads();                                    // B1: wsum + hist zero done

    if (warp == 0) {                                    // n_present = total presence
        int v = s_wsum[lane];
        #pragma unroll
        for (int o = 16; o; o >>= 1) v += __shfl_down_sync(0xFFFFFFFFu, v, o);
        if (lane == 0) s_scal[0] = v;
    }
    // histogram of absent-priority digits (uniform -> ~1 key/bin, low contention)
    #pragma unroll
    for (int j = 0; j < PT; j++)
        if (!presf[j]) atomicAdd(&s_hist[digr[j]], 1);
    __syncthreads();                                    // B2: hist + n_present done

    const int n_present = s_scal[0];
    const int n_neg = K - n_present;

    // ---- winner-bin search via block scan over 4096 bins ----
    int4 cc = ((int4*)s_hist)[tid];
    int cb[4] = {cc.x, cc.y, cc.z, cc.w};
    int tot = cb[0] + cb[1] + cb[2] + cb[3];
    int sc = tot;
    #pragma unroll
    for (int o = 1; o < 32; o <<= 1) {
        int v = __shfl_up_sync(0xFFFFFFFFu, sc, o);
        if (lane >= o) sc += v;
    }
    if (lane == 31) s_wsum[warp] = sc;
    __syncthreads();                                    // B3
    if (warp == 0) {
        int v = s_wsum[lane];
        int vs = v;
        #pragma unroll
        for (int o = 1; o < 32; o <<= 1) {
            int t2 = __shfl_up_sync(0xFFFFFFFFu, vs, o);
            if (lane >= o) vs += t2;
        }
        s_wsum[lane] = vs - v;
    }
    __syncthreads();                                    // B4
    if (n_neg > 0) {
        int cum = s_wsum[warp] + (sc - tot);
        #pragma unroll
        for (int j = 0; j < 4; j++) {
            if (cum < n_neg && n_neg <= cum + cb[j]) {
                s_scal[1] = tid * 4 + j;
                s_scal[2] = n_neg - cum;
                s_scal[3] = cb[j];
            }
            cum += cb[j];
        }
    }
    __syncthreads();                                    // B5
    const int winbin = s_scal[1];
    const int t_rem  = s_scal[2];
    const int cnt_eq = s_scal[3];
    const bool need_exact = (winbin >= 0) && (t_rem < cnt_eq);

    // ---- exact stable tie-break candidates (rare; uniform branch) ----
    int* s_cand = s_hist;
    if (need_exact) {
        #pragma unroll
        for (int j = 0; j < PT; j++)
            if (!presf[j] && digr[j] == winbin)
                s_cand[atomicAdd(&s_scal[4], 1)] = base + j;
        __syncthreads();                                // B6
    }

    // ---- keep decision + compaction scan -> scatter packed indices ----
    int keep[PT];
    sum = 0;
    #pragma unroll
    for (int j = 0; j < PT; j++) {
        bool kp;
        if (presf[j]) kp = true;
        else if (winbin < 0) kp = false;
        else {
            int d = digr[j];
            if (d < winbin) kp = true;
            else if (d > winbin) kp = false;
            else if (!need_exact) kp = true;
            else {
                unsigned int my = s_keys[base + j];
                int myi = base + j, r = 0, nc = s_scal[4];
                for (int t = 0; t < nc; t++) {
                    int ci = s_cand[t];
                    unsigned int ck = s_keys[ci];
                    r += (ck < my) || (ck == my && ci < myi);
                }
                kp = (r < t_rem);                       // stable (key, idx) rank
            }
        }
        keep[j] = kp ? 1 : 0;
        local[j] = sum;
        sum += keep[j];
    }
    ws = sum;
    #pragma unroll
    for (int o = 1; o < 32; o <<= 1) {
        int v = __shfl_up_sync(0xFFFFFFFFu, ws, o);
        if (lane >= o) ws += v;
    }
    if (lane == 31) s_wsum[warp] = ws;
    __syncthreads();                                    // B7
    if (warp == 0) {
        int v = s_wsum[lane];
        int vs = v;
        #pragma unroll
        for (int o = 1; o < 32; o <<= 1) {
            int t2 = __shfl_up_sync(0xFFFFFFFFu, vs, o);
            if (lane >= o) vs += t2;
        }
        s_wsum[lane] = vs - v;
    }
    __syncthreads();                                    // B8
    {
        int tb = s_wsum[warp] + (ws - sum);
        #pragma unroll
        for (int j = 0; j < PT; j++)
            if (keep[j]) {
                int p = tb + local[j];
                if (p < KPAD)
                    g_idx[b * KPAD + p] = (base + j) | (presf[j] << 15);
            }
    }
}

// ======================= Kernel B: high-occupancy gather =======================
__global__ __launch_bounds__(TPB_B) void gather_kernel(
    const float* __restrict__ z_where,
    const float* __restrict__ z_what_loc,
    const float* __restrict__ z_depth_loc,
    float* __restrict__ out,
    int B, int K, int pc)
{
    __shared__ int s_e[256];

    const int b      = blockIdx.x;
    const int pstart = blockIdx.y * pc;
    const int pend   = min(K, pstart + pc);
    const int n      = pend - pstart;
    const int tid    = threadIdx.x;

    for (int t = tid; t < n; t += TPB_B)
        s_e[t] = g_idx[b * KPAD + pstart + t];
    __syncthreads();

    float* out_where = out;                             // [B, K, 4]
    float* out_mod   = out + (size_t)B * K * 4;         // [B, K, 1]
    float* out_what  = out + (size_t)B * K * 5;         // [B, K, 64]
    float* out_depth = out + (size_t)B * K * 69;        // [B, K, 1]

    const float4* zw4 = (const float4*)z_where + (size_t)b * NSLOTS;
    const float*  zd  = z_depth_loc + (size_t)b * NSLOTS;

    for (int t = tid; t < n; t += TPB_B) {
        int p = pstart + t;
        int e = s_e[t];
        int slot = e & 0xFFF;
        bool pres = (e & 0x8000) != 0;
        float4 w = __ldg(&zw4[slot]);
        float m = fmaxf(w.z, w.w);
        ((float4*)out_where)[(size_t)b * K + p] = make_float4(w.x, w.y, m, m);
        out_mod[(size_t)b * K + p]   = pres ? 1.0f : -1.0f;
        out_depth[(size_t)b * K + p] = pres ? __ldg(&zd[slot]) : 0.0f;
    }

    const float4* wl4 = (const float4*)z_what_loc + (size_t)b * NSLOTS * 16;
    float4* ow4 = (float4*)out_what + (size_t)b * K * 16;
    const int total = n * 16;
    for (int i = tid; i < total; i += TPB_B) {
        int t = i >> 4;
        int c = i & 15;
        int e = s_e[t];
        float4 v = make_float4(0.f, 0.f, 0.f, 0.f);
        if (e & 0x8000) v = __ldg(&wl4[(e & 0xFFF) * 16 + c]);
        ow4[(size_t)(pstart + t) * 16 + c] = v;
    }
}

extern "C" void kernel_launch(void* const* d_in, const int* in_sizes, int n_in,
                              void* d_out, int out_size) {
    const float* z_where      = (const float*)d_in[0];
    const float* z_present    = (const float*)d_in[1];
    const float* z_what_loc   = (const float*)d_in[2];
    // d_in[3] = z_what_scale  (never read)
    const float* z_depth_loc  = (const float*)d_in[4];
    // d_in[5] = z_depth_scale (never read)
    const float* neg_priority = (const float*)d_in[6];

    const int B = in_sizes[6] / NSLOTS;
    const int K = out_size / (B * 70);
    const int pc = (K + NSLICE - 1) / NSLICE;

    select_kernel<<<B, TPB_A>>>(z_present, neg_priority, K);
    gather_kernel<<<dim3(B, NSLICE), TPB_B>>>(z_where, z_what_loc, z_depth_loc,
                                              (float*)d_out, B, K, pc);
}

// round 7
// speedup vs baseline: 1.1830x; 1.1830x over previous
#include <cuda_runtime.h>
#include <stdint.h>

#define NSLOTS 4096
#define TPB 1024
#define PT 4            // NSLOTS / TPB
#define NBINS 4096
#define KPAD 672
#define EPSF 1e-3f

__global__ __launch_bounds__(TPB) void latent_handler_kernel(
    const float* __restrict__ z_where,
    const float* __restrict__ z_present,
    const float* __restrict__ z_what_loc,
    const float* __restrict__ z_depth_loc,
    const float* __restrict__ neg_priority,
    float* __restrict__ out,
    int B, int K)
{
    __shared__ unsigned int s_keys[NSLOTS];   // 16KB
    __shared__ int s_hist[NBINS];             // 16KB (reused as candidate list)
    __shared__ int s_idxmap[KPAD];            // packed: slot | (present << 15)
    __shared__ int s_wsum[32];
    __shared__ int s_scal[8];

    const int b    = blockIdx.x;
    const int tid  = threadIdx.x;
    const int lane = tid & 31;
    const int warp = tid >> 5;
    const int base = tid * PT;

    // ================= selection (lean, 9 barriers total) =================
    int presf[PT], local[PT], digr[PT];
    int sum = 0;
    {
        float4 p = ((const float4*)(z_present    + (size_t)b * NSLOTS))[tid];
        float4 q = ((const float4*)(neg_priority + (size_t)b * NSLOTS))[tid];
        float pv[4] = {p.x, p.y, p.z, p.w};
        float qv[4] = {q.x, q.y, q.z, q.w};
        #pragma unroll
        for (int j = 0; j < PT; j++) {
            bool pres = pv[j] > EPSF;
            presf[j] = pres ? 1 : 0;
            local[j] = sum;
            sum += presf[j];
            unsigned int bits = __float_as_uint(qv[j]);
            unsigned int msk  = (unsigned int)(((int)bits) >> 31) | 0x80000000u;
            s_keys[base + j] = pres ? 0xFFFFFFFFu : (bits ^ msk);
            int d = __float2int_rd(qv[j] * 4096.0f);   // exact ×2^12, monotone
            digr[j] = min(NBINS - 1, max(0, d));
        }
    }
    ((int4*)s_hist)[tid] = make_int4(0, 0, 0, 0);       // zero histogram
    int ws = sum;
    #pragma unroll
    for (int o = 1; o < 32; o <<= 1) {
        int v = __shfl_up_sync(0xFFFFFFFFu, ws, o);
        if (lane >= o) ws += v;
    }
    if (lane == 31) s_wsum[warp] = ws;
    if (tid == 0) { s_scal[1] = -1; s_scal[4] = 0; }
    __syncthreads();                                    // B1

    if (warp == 0) {                                    // n_present total
        int v = s_wsum[lane];
        #pragma unroll
        for (int o = 16; o; o >>= 1) v += __shfl_down_sync(0xFFFFFFFFu, v, o);
        if (lane == 0) s_scal[0] = v;
    }
    #pragma unroll
    for (int j = 0; j < PT; j++)
        if (!presf[j]) atomicAdd(&s_hist[digr[j]], 1);  // uniform bins, low contention
    __syncthreads();                                    // B2

    const int n_present = s_scal[0];
    const int n_neg = K - n_present;

    // winner-bin search: block scan over 4096 bins
    int4 cc = ((int4*)s_hist)[tid];
    int cb[4] = {cc.x, cc.y, cc.z, cc.w};
    int tot = cb[0] + cb[1] + cb[2] + cb[3];
    int sc = tot;
    #pragma unroll
    for (int o = 1; o < 32; o <<= 1) {
        int v = __shfl_up_sync(0xFFFFFFFFu, sc, o);
        if (lane >= o) sc += v;
    }
    if (lane == 31) s_wsum[warp] = sc;
    __syncthreads();                                    // B3
    if (warp == 0) {
        int v = s_wsum[lane];
        int vs = v;
        #pragma unroll
        for (int o = 1; o < 32; o <<= 1) {
            int t2 = __shfl_up_sync(0xFFFFFFFFu, vs, o);
            if (lane >= o) vs += t2;
        }
        s_wsum[lane] = vs - v;
    }
    __syncthreads();                                    // B4
    if (n_neg > 0) {
        int cum = s_wsum[warp] + (sc - tot);
        #pragma unroll
        for (int j = 0; j < 4; j++) {
            if (cum < n_neg && n_neg <= cum + cb[j]) {
                s_scal[1] = tid * 4 + j;
                s_scal[2] = n_neg - cum;
                s_scal[3] = cb[j];
            }
            cum += cb[j];
        }
    }
    __syncthreads();                                    // B5
    const int winbin = s_scal[1];
    const int t_rem  = s_scal[2];
    const int cnt_eq = s_scal[3];
    const bool need_exact = (winbin >= 0) && (t_rem < cnt_eq);

    int* s_cand = s_hist;                               // reuse
    if (need_exact) {
        #pragma unroll
        for (int j = 0; j < PT; j++)
            if (!presf[j] && digr[j] == winbin)
                s_cand[atomicAdd(&s_scal[4], 1)] = base + j;
        __syncthreads();                                // B6 (uniform branch)
    }

    // keep decision + compaction scan -> packed idxmap
    int keep[PT];
    sum = 0;
    #pragma unroll
    for (int j = 0; j < PT; j++) {
        bool kp;
        if (presf[j]) kp = true;
        else if (winbin < 0) kp = false;
        else {
            int d = digr[j];
            if (d < winbin) kp = true;
            else if (d > winbin) kp = false;
            else if (!need_exact) kp = true;
            else {
                unsigned int my = s_keys[base + j];
                int myi = base + j, r = 0, nc = s_scal[4];
                for (int t = 0; t < nc; t++) {
                    int ci = s_cand[t];
                    unsigned int ck = s_keys[ci];
                    r += (ck < my) || (ck == my && ci < myi);
                }
                kp = (r < t_rem);                       // stable (key, idx) rank
            }
        }
        keep[j] = kp ? 1 : 0;
        local[j] = sum;
        sum += keep[j];
    }
    ws = sum;
    #pragma unroll
    for (int o = 1; o < 32; o <<= 1) {
        int v = __shfl_up_sync(0xFFFFFFFFu, ws, o);
        if (lane >= o) ws += v;
    }
    if (lane == 31) s_wsum[warp] = ws;
    __syncthreads();                                    // B7
    if (warp == 0) {
        int v = s_wsum[lane];
        int vs = v;
        #pragma unroll
        for (int o = 1; o < 32; o <<= 1) {
            int t2 = __shfl_up_sync(0xFFFFFFFFu, vs, o);
            if (lane >= o) vs += t2;
        }
        s_wsum[lane] = vs - v;
    }
    __syncthreads();                                    // B8
    {
        int tb = s_wsum[warp] + (ws - sum);
        #pragma unroll
        for (int j = 0; j < PT; j++)
            if (keep[j]) {
                int p = tb + local[j];
                if (p < KPAD)
                    s_idxmap[p] = (base + j) | (presf[j] << 15);
            }
    }
    __syncthreads();                                    // B9

    // ================= epilogue: MLP-batched gather + stream =================
    float* out_where = out;                             // [B, K, 4]
    float* out_mod   = out + (size_t)B * K * 4;         // [B, K, 1]
    float* out_what  = out + (size_t)B * K * 5;         // [B, K, 64]
    float* out_depth = out + (size_t)B * K * 69;        // [B, K, 1]

    const float4* zw4 = (const float4*)z_where + (size_t)b * NSLOTS;
    const float*  zd  = z_depth_loc + (size_t)b * NSLOTS;

    // K < TPB: exactly one entry per thread
    for (int p = tid; p < K; p += TPB) {
        int e = s_idxmap[p];
        int slot = e & 0xFFF;
        bool pres = (e & 0x8000) != 0;
        float4 w = __ldg(&zw4[slot]);
        float m = fmaxf(w.z, w.w);
        ((float4*)out_where)[(size_t)b * K + p] = make_float4(w.x, w.y, m, m);
        out_mod[(size_t)b * K + p]   = pres ? 1.0f : -1.0f;
        out_depth[(size_t)b * K + p] = pres ? __ldg(&zd[slot]) : 0.0f;
    }

    const float4* wl4 = (const float4*)z_what_loc + (size_t)b * NSLOTS * 16;
    float4* ow4 = (float4*)out_what + (size_t)b * K * 16;
    const int total = K * 16;
    const int c = tid & 15;                             // loop-invariant column
    int i = tid;
    // batches of 4 for MLP
    for (; i + 3 * TPB < total; i += 4 * TPB) {
        int e0 = s_idxmap[(i           ) >> 4];
        int e1 = s_idxmap[(i +     TPB ) >> 4];
        int e2 = s_idxmap[(i + 2 * TPB ) >> 4];
        int e3 = s_idxmap[(i + 3 * TPB ) >> 4];
        float4 v0 = make_float4(0.f, 0.f, 0.f, 0.f);
        float4 v1 = v0, v2 = v0, v3 = v0;
        if (e0 & 0x8000) v0 = __ldg(&wl4[(e0 & 0xFFF) * 16 + c]);
        if (e1 & 0x8000) v1 = __ldg(&wl4[(e1 & 0xFFF) * 16 + c]);
        if (e2 & 0x8000) v2 = __ldg(&wl4[(e2 & 0xFFF) * 16 + c]);
        if (e3 & 0x8000) v3 = __ldg(&wl4[(e3 & 0xFFF) * 16 + c]);
        ow4[i          ] = v0;
        ow4[i +     TPB] = v1;
        ow4[i + 2 * TPB] = v2;
        ow4[i + 3 * TPB] = v3;
    }
    for (; i < total; i += TPB) {
        int e = s_idxmap[i >> 4];
        float4 v = make_float4(0.f, 0.f, 0.f, 0.f);
        if (e & 0x8000) v = __ldg(&wl4[(e & 0xFFF) * 16 + c]);
        ow4[i] = v;
    }
}

extern "C" void kernel_launch(void* const* d_in, const int* in_sizes, int n_in,
                              void* d_out, int out_size) {
    const float* z_where      = (const float*)d_in[0];
    const float* z_present    = (const float*)d_in[1];
    const float* z_what_loc   = (const float*)d_in[2];
    // d_in[3] = z_what_scale  (never read)
    const float* z_depth_loc  = (const float*)d_in[4];
    // d_in[5] = z_depth_scale (never read)
    const float* neg_priority = (const float*)d_in[6];

    const int B = in_sizes[6] / NSLOTS;
    const int K = out_size / (B * 70);

    latent_handler_kernel<<<B, TPB>>>(z_where, z_present, z_what_loc,
                                      z_depth_loc, neg_priority,
                                      (float*)d_out, B, K);
}